// round 1
// baseline (speedup 1.0000x reference)
#include <cuda_runtime.h>
#include <cstddef>

// Problem constants (fixed by the dataset)
#define BS    32
#define NFEAT 64
#define NN    512      // N (graph nodes)
#define JJ    4
#define NOUT  128
#define ROWF4 512      // one W row (m*j = 2048 floats) = 512 float4
#define NCHUNK 32      // n-chunks per batch in kernel 1
#define NPERCHUNK (NN / NCHUNK)   // 16

// Scratch: per-(b,chunk) partial sums of W over n. 32*32*2048 floats = 8 MB.
__device__ float g_Spart[BS * NCHUNK * 2048];

// ---------------------------------------------------------------------------
// Kernel 1: S_partial[b,chunk,m*4+j] = sum over 16 n-rows of W[b,n,m,j]
// W layout: [b][n][m][j], row (m,j) is 2048 contiguous floats = 512 float4.
// Fully coalesced: 512 threads x float4 = one whole 8KB row per iteration.
// ---------------------------------------------------------------------------
__global__ __launch_bounds__(512) void reduce_w_kernel(const float4* __restrict__ W4) {
    const int b     = blockIdx.x;
    const int chunk = blockIdx.y;
    const int t     = threadIdx.x;          // 0..511

    const size_t row0 = ((size_t)b * NN + (size_t)chunk * NPERCHUNK) * ROWF4;
    const float4* __restrict__ base = W4 + row0;

    float4 acc = make_float4(0.f, 0.f, 0.f, 0.f);
#pragma unroll
    for (int i = 0; i < NPERCHUNK; ++i) {
        // streaming read, evict-first: W is read exactly once, larger than L2
        float4 v = __ldcs(&base[(size_t)i * ROWF4 + t]);
        acc.x += v.x; acc.y += v.y; acc.z += v.z; acc.w += v.w;
    }

    float4* out4 = reinterpret_cast<float4*>(g_Spart);
    out4[((size_t)b * NCHUNK + chunk) * ROWF4 + t] = acc;
}

// ---------------------------------------------------------------------------
// Kernel 2: per batch b —
//   S[m*4+j]   = sum over 32 chunks of g_Spart
//   G[j*64+f]  = sum_m S[m*4+j] * X[b,f,m]
//   y[b,o]     = sum_c fc_w[o,c]*G[c] + 512*fc_b[o]
// 32 blocks x 256 threads. All tiny vs kernel 1.
// ---------------------------------------------------------------------------
__global__ __launch_bounds__(256) void finalize_kernel(
    const float* __restrict__ X,
    const float* __restrict__ fc_w,
    const float* __restrict__ fc_b,
    float* __restrict__ out)
{
    __shared__ float Ssh[2048];
    __shared__ float Xs[64][65];   // +1 pad: lanes stride rows -> conflict-free
    __shared__ float Gsh[256];

    const int b = blockIdx.x;
    const int t = threadIdx.x;     // 0..255

    // 1) reduce the 32 chunk-partials for this batch
    const float* __restrict__ part = g_Spart + (size_t)b * NCHUNK * 2048;
#pragma unroll
    for (int i = 0; i < 8; ++i) {
        const int slot = t + i * 256;
        float a = 0.f;
#pragma unroll
        for (int c = 0; c < NCHUNK; ++c) a += part[(size_t)c * 2048 + slot];
        Ssh[slot] = a;             // Ssh[m*4+j]
    }

    // 2) G[j*64+f] = sum_m Ssh[m*4+j] * X[b,f,m], tiled over m in shared
    const int j = t >> 6;          // 0..3
    const int f = t & 63;          // 0..63
    const float* __restrict__ Xb = X + (size_t)b * NFEAT * NN;

    float g = 0.f;
    for (int tile = 0; tile < NN / 64; ++tile) {
        __syncthreads();           // protects Ssh (1st iter) and Xs reuse
#pragma unroll
        for (int i = 0; i < 16; ++i) {
            const int idx = t + i * 256;       // 0..4095
            const int ff  = idx >> 6;
            const int mm  = idx & 63;
            Xs[ff][mm] = Xb[(size_t)ff * NN + tile * 64 + mm];
        }
        __syncthreads();
#pragma unroll
        for (int mm = 0; mm < 64; ++mm) {
            // Ssh index uniform per-warp (broadcast), Xs padded (no conflicts)
            g += Ssh[(tile * 64 + mm) * 4 + j] * Xs[f][mm];
        }
    }
    Gsh[t] = g;
    __syncthreads();

    // 3) y[b,o] = fc_w[o,:] . G + 512*fc_b[o]
    if (t < NOUT) {
        float y = (float)NN * fc_b[t];
        const float* __restrict__ wrow = fc_w + (size_t)t * (JJ * NFEAT);
#pragma unroll 8
        for (int c = 0; c < JJ * NFEAT; ++c) y += wrow[c] * Gsh[c];
        out[(size_t)b * NOUT + t] = y;
    }
}

// ---------------------------------------------------------------------------
// Inputs (metadata order): X[32,64,512] f32, W[32,512,512,4] f32,
// fc_w[128,256] f32, fc_b[128] f32, N_batch (int), mask[32,512] f32 (unused).
// Output: y[32,128] f32.
// ---------------------------------------------------------------------------
extern "C" void kernel_launch(void* const* d_in, const int* in_sizes, int n_in,
                              void* d_out, int out_size)
{
    const float* X    = (const float*)d_in[0];
    const float* W    = (const float*)d_in[1];
    const float* fc_w = (const float*)d_in[2];
    const float* fc_b = (const float*)d_in[3];
    float*       out  = (float*)d_out;

    dim3 grid1(BS, NCHUNK);
    reduce_w_kernel<<<grid1, 512>>>(reinterpret_cast<const float4*>(W));
    finalize_kernel<<<BS, 256>>>(X, fc_w, fc_b, out);
}

// round 2
// speedup vs baseline: 1.1129x; 1.1129x over previous
#include <cuda_runtime.h>
#include <cstddef>

// Problem constants (fixed by the dataset)
#define BS    32
#define NFEAT 64
#define NN    512      // N (graph nodes)
#define JJ    4
#define NOUT  128
#define CDIM  (JJ * NFEAT)        // 256 channels
#define ROWF4 512                 // one W row (m,j) = 2048 floats = 512 float4
#define NCHUNK 32                 // n-chunks per batch in kernel 1
#define NPERCHUNK (NN / NCHUNK)   // 16

// Scratch 1: per-(b,chunk) partial sums of W over n. 32*32*2048 floats = 8 MB.
__device__ float g_Spart[BS * NCHUNK * 2048];
// Scratch 2: fully reduced S[b][m*4+j]. 32*2048 floats = 256 KB.
__device__ float g_S[BS * 2048];

// ---------------------------------------------------------------------------
// Kernel 1: S_partial[b,chunk,m*4+j] = sum over 16 n-rows of W[b,n,m,j]
// W layout: [b][n][m][j]; one n-row (all m,j) = 2048 contiguous floats.
// 512 threads x float4 = one whole 8KB row per iteration, fully coalesced.
// ---------------------------------------------------------------------------
__global__ __launch_bounds__(512) void reduce_w_kernel(const float4* __restrict__ W4) {
    const int b     = blockIdx.x;
    const int chunk = blockIdx.y;
    const int t     = threadIdx.x;          // 0..511

    const size_t row0 = ((size_t)b * NN + (size_t)chunk * NPERCHUNK) * ROWF4;
    const float4* __restrict__ base = W4 + row0;

    float4 acc = make_float4(0.f, 0.f, 0.f, 0.f);
#pragma unroll
    for (int i = 0; i < NPERCHUNK; ++i) {
        // streaming, evict-first: W is read exactly once and is larger than L2
        float4 v = __ldcs(&base[(size_t)i * ROWF4 + t]);
        acc.x += v.x; acc.y += v.y; acc.z += v.z; acc.w += v.w;
    }

    float4* out4 = reinterpret_cast<float4*>(g_Spart);
    out4[((size_t)b * NCHUNK + chunk) * ROWF4 + t] = acc;
}

// ---------------------------------------------------------------------------
// Kernel 2: S[b][slot] = sum over 32 chunks of g_Spart[b][c][slot]
// grid = (BS, 8), 256 threads; each thread owns one slot. For a fixed chunk c
// consecutive threads read contiguous floats -> fully coalesced, unroll-32 MLP.
// 8 MB total read spread over 256 blocks.
// ---------------------------------------------------------------------------
__global__ __launch_bounds__(256) void reduce_chunks_kernel() {
    const int b    = blockIdx.x;
    const int slot = blockIdx.y * 256 + threadIdx.x;   // 0..2047

    const float* __restrict__ part = g_Spart + (size_t)b * NCHUNK * 2048 + slot;
    float a = 0.f;
#pragma unroll
    for (int c = 0; c < NCHUNK; ++c) a += part[(size_t)c * 2048];
    g_S[(size_t)b * 2048 + slot] = a;
}

// ---------------------------------------------------------------------------
// Kernel 3: per batch b —
//   G[j*64+f] = sum_m S[b][m*4+j] * X[b,f,m]
//   y[b,o]    = sum_c fc_w[o,c]*G[c] + 512*fc_b[o]
// Only reads 8 KB of S + 128 KB of X per block now.
// ---------------------------------------------------------------------------
#define MTILE 128
__global__ __launch_bounds__(256) void finalize_kernel(
    const float* __restrict__ X,
    const float* __restrict__ fc_w,
    const float* __restrict__ fc_b,
    float* __restrict__ out)
{
    __shared__ float Ssh[2048];               // S[m*4+j] for this batch
    __shared__ float Xs[NFEAT][MTILE + 1];    // padded: stride 129 (odd) -> conflict-free
    __shared__ float Gsh[CDIM];

    const int b = blockIdx.x;
    const int t = threadIdx.x;     // 0..255
    const int j = t >> 6;          // 0..3   (uniform per warp -> S reads broadcast)
    const int f = t & 63;          // 0..63

    // load S for this batch (8 KB, coalesced float4)
    {
        const float4* __restrict__ S4 = reinterpret_cast<const float4*>(g_S + (size_t)b * 2048);
        float4* __restrict__ Ssh4 = reinterpret_cast<float4*>(Ssh);
#pragma unroll
        for (int i = 0; i < 2; ++i) Ssh4[t + i * 256] = S4[t + i * 256];
    }

    const float* __restrict__ Xb = X + (size_t)b * NFEAT * NN;

    float g = 0.f;
#pragma unroll
    for (int tile = 0; tile < NN / MTILE; ++tile) {
        __syncthreads();
        // stage X[:, tile*128 .. +128) into shared: 64x128 floats = 32 KB, float4 coalesced
        const float4* __restrict__ Xb4 = reinterpret_cast<const float4*>(Xb);
#pragma unroll
        for (int i = 0; i < 8; ++i) {
            const int idx = t + i * 256;              // 0..2047 float4 slots
            const int ff  = idx >> 5;                 // /32: 32 float4 per row-tile
            const int mq  = idx & 31;
            float4 v = Xb4[(size_t)ff * (NN / 4) + tile * (MTILE / 4) + mq];
            Xs[ff][mq * 4 + 0] = v.x;
            Xs[ff][mq * 4 + 1] = v.y;
            Xs[ff][mq * 4 + 2] = v.z;
            Xs[ff][mq * 4 + 3] = v.w;
        }
        __syncthreads();
#pragma unroll 8
        for (int mm = 0; mm < MTILE; ++mm) {
            // Ssh index uniform per warp (broadcast); Xs stride-129 (conflict-free)
            g += Ssh[(tile * MTILE + mm) * 4 + j] * Xs[f][mm];
        }
    }
    Gsh[t] = g;
    __syncthreads();

    // y[b,o] = fc_w[o,:] . G + 512*fc_b[o]
    if (t < NOUT) {
        float y = (float)NN * fc_b[t];
        const float* __restrict__ wrow = fc_w + (size_t)t * CDIM;
#pragma unroll 8
        for (int c = 0; c < CDIM; ++c) y += wrow[c] * Gsh[c];
        out[(size_t)b * NOUT + t] = y;
    }
}

// ---------------------------------------------------------------------------
// Inputs (metadata order): X[32,64,512] f32, W[32,512,512,4] f32,
// fc_w[128,256] f32, fc_b[128] f32, N_batch (int), mask[32,512] f32 (unused).
// Output: y[32,128] f32.
// ---------------------------------------------------------------------------
extern "C" void kernel_launch(void* const* d_in, const int* in_sizes, int n_in,
                              void* d_out, int out_size)
{
    const float* X    = (const float*)d_in[0];
    const float* W    = (const float*)d_in[1];
    const float* fc_w = (const float*)d_in[2];
    const float* fc_b = (const float*)d_in[3];
    float*       out  = (float*)d_out;

    dim3 grid1(BS, NCHUNK);
    reduce_w_kernel<<<grid1, 512>>>(reinterpret_cast<const float4*>(W));
    dim3 grid2(BS, 8);
    reduce_chunks_kernel<<<grid2, 256>>>();
    finalize_kernel<<<BS, 256>>>(X, fc_w, fc_b, out);
}

// round 3
// speedup vs baseline: 1.5041x; 1.3515x over previous
#include <cuda_runtime.h>
#include <cstddef>

// Problem constants (fixed by the dataset)
#define BS    32
#define NFEAT 64
#define NN    512      // N (graph nodes / m dim)
#define JJ    4
#define NOUT  128
#define CDIM  (JJ * NFEAT)   // 256 channels
#define ROWF4 512            // one W n-row = 2048 floats = 512 float4 (float4 q <-> m=q, j=0..3)

// S stored transposed: S[b][j][m]  (32*4*512 floats = 256 KB)
__device__ float g_S[BS * JJ * NN];
// G[b][c],  c = j*64+f  (32*256 floats = 32 KB)
__device__ float g_G[BS * CDIM];

// ---------------------------------------------------------------------------
// Kernel 1: S[b][j][m] = sum_n W[b,n,m,j], written directly (no partials).
// Column-split: block (b, s16) owns float4 columns [s16*32, s16*32+32) of every
// n-row. Each warp's load = 32 consecutive float4 = 512B = 4 full sectors.
// 8 n-subgroups per block accumulate in registers; tiny shared tree-reduce.
// W float4 slot q in a row covers floats m*4+j with m=q, j=0..3 -> components
// ARE the j index, so the [b][j][m] transpose is free on the final store.
// ---------------------------------------------------------------------------
__global__ __launch_bounds__(256) void reduce_w_kernel(const float4* __restrict__ W4) {
    __shared__ float4 red[256];

    const int b   = blockIdx.x;
    const int s16 = blockIdx.y;              // 0..15
    const int t   = threadIdx.x;             // 0..255
    const int lane32 = t & 31;
    const int ng     = t >> 5;               // n-subgroup 0..7

    const int slot4 = s16 * 32 + lane32;     // float4 column = m index
    const float4* __restrict__ base = W4 + ((size_t)b * NN) * ROWF4 + slot4;

    float4 acc = make_float4(0.f, 0.f, 0.f, 0.f);
#pragma unroll 8
    for (int i = 0; i < 64; ++i) {
        const int n = i * 8 + ng;
        float4 v = __ldcs(&base[(size_t)n * ROWF4]);   // streaming, read-once
        acc.x += v.x; acc.y += v.y; acc.z += v.z; acc.w += v.w;
    }

    red[t] = acc;
    __syncthreads();
#pragma unroll
    for (int s = 128; s >= 32; s >>= 1) {
        if (t < s) {
            float4 o = red[t + s];
            red[t].x += o.x; red[t].y += o.y; red[t].z += o.z; red[t].w += o.w;
        }
        __syncthreads();
    }

    if (t < 32) {
        const int m = s16 * 32 + t;
        const float4 r = red[t];
        g_S[((size_t)b * JJ + 0) * NN + m] = r.x;
        g_S[((size_t)b * JJ + 1) * NN + m] = r.y;
        g_S[((size_t)b * JJ + 2) * NN + m] = r.z;
        g_S[((size_t)b * JJ + 3) * NN + m] = r.w;
    }
}

// ---------------------------------------------------------------------------
// Kernel 2: G[b][j*64+f] = sum_m S[b][j][m] * X[b][f][m]
// grid (32 b, 32 cgroups) x 256 thr; one warp per output c. Both streams
// coalesced (m = lane + 32*i), shfl tree-reduce. All L2-hot except X (4 MB).
// ---------------------------------------------------------------------------
__global__ __launch_bounds__(256) void compute_g_kernel(const float* __restrict__ X) {
    const int b    = blockIdx.x;
    const int c    = blockIdx.y * 8 + (threadIdx.x >> 5);  // 0..255
    const int lane = threadIdx.x & 31;
    const int j    = c >> 6;
    const int f    = c & 63;

    const float* __restrict__ Sr = g_S + ((size_t)b * JJ + j) * NN;
    const float* __restrict__ Xr = X   + ((size_t)b * NFEAT + f) * NN;

    float a = 0.f;
#pragma unroll
    for (int i = 0; i < 16; ++i) {
        const int m = i * 32 + lane;
        a += Sr[m] * Xr[m];
    }
#pragma unroll
    for (int s = 16; s > 0; s >>= 1) a += __shfl_xor_sync(0xffffffffu, a, s);

    if (lane == 0) g_G[(size_t)b * CDIM + c] = a;
}

// ---------------------------------------------------------------------------
// Kernel 3: y[b][o] = sum_c fc_w[o][c] * G[b][c] + 512 * fc_b[o]
// grid 32 x 128 thr; float4 loads, everything L2-hot, trivial.
// ---------------------------------------------------------------------------
__global__ __launch_bounds__(128) void compute_y_kernel(
    const float* __restrict__ fc_w,
    const float* __restrict__ fc_b,
    float* __restrict__ out)
{
    const int b = blockIdx.x;
    const int o = threadIdx.x;   // 0..127

    const float4* __restrict__ w4 = reinterpret_cast<const float4*>(fc_w + (size_t)o * CDIM);
    const float4* __restrict__ g4 = reinterpret_cast<const float4*>(g_G + (size_t)b * CDIM);

    float y = (float)NN * fc_b[o];
#pragma unroll
    for (int q = 0; q < CDIM / 4; ++q) {
        const float4 w = w4[q];
        const float4 g = g4[q];
        y += w.x * g.x + w.y * g.y + w.z * g.z + w.w * g.w;
    }
    out[(size_t)b * NOUT + o] = y;
}

// ---------------------------------------------------------------------------
// Inputs (metadata order): X[32,64,512] f32, W[32,512,512,4] f32,
// fc_w[128,256] f32, fc_b[128] f32, N_batch (int), mask[32,512] f32 (unused).
// Output: y[32,128] f32.
// ---------------------------------------------------------------------------
extern "C" void kernel_launch(void* const* d_in, const int* in_sizes, int n_in,
                              void* d_out, int out_size)
{
    const float* X    = (const float*)d_in[0];
    const float* W    = (const float*)d_in[1];
    const float* fc_w = (const float*)d_in[2];
    const float* fc_b = (const float*)d_in[3];
    float*       out  = (float*)d_out;

    dim3 grid1(BS, 16);
    reduce_w_kernel<<<grid1, 256>>>(reinterpret_cast<const float4*>(W));
    dim3 grid2(BS, 32);
    compute_g_kernel<<<grid2, 256>>>(X);
    compute_y_kernel<<<BS, 128>>>(fc_w, fc_b, out);
}